// round 1
// baseline (speedup 1.0000x reference)
#include <cuda_runtime.h>
#include <cuda_bf16.h>
#include <cstdint>

// ---------------- problem constants ----------------
#define N0v 200000
#define N1v 100000
#define N2v 80000
#define Fv  32
#define K5v 125
#define K3v 27
#define M1v 20000
#define M2v 20000
#define M3v 30000
#define M4v 20000
#define EPSv 1e-5f

// ---------------- scratch (device globals; no allocs allowed) ----------------
__device__ float g_buf1[N1v * 32];    // 12.8 MB
__device__ float g_buf2[N1v * 32];    // 12.8 MB
__device__ float g_buf3[N2v * 64];    // 20.5 MB
__device__ float g_buf4[N2v * 128];   // 41.0 MB
__device__ float g_buf5[N2v * 256];   // 82.0 MB
__device__ float g_sum[256];
__device__ float g_sumsq[256];

// ---------------- vector reductions ----------------
__device__ __forceinline__ void red4(float* p, float a, float b, float c, float d) {
    asm volatile("red.global.add.v4.f32 [%0], {%1,%2,%3,%4};"
                 :: "l"(p), "f"(a), "f"(b), "f"(c), "f"(d) : "memory");
}
__device__ __forceinline__ void red2(float* p, float a, float b) {
    asm volatile("red.global.add.v2.f32 [%0], {%1,%2};"
                 :: "l"(p), "f"(a), "f"(b) : "memory");
}

// ---------------- conv1a: CIN=1 special case ----------------
// one thread per (k*M+m, cout-group-of-4)
__global__ void conv1a_kernel(const float* __restrict__ x,
                              const float* __restrict__ w,   // [K5,1,32]
                              const int* __restrict__ in_idx,
                              const int* __restrict__ out_idx,
                              float* __restrict__ out,
                              int total, int M) {
    int gid = blockIdx.x * blockDim.x + threadIdx.x;
    int pair = gid >> 3;
    if (pair >= total) return;
    int g = gid & 7;
    int k = pair / M;
    float v = x[in_idx[pair]];
    float4 wv = *reinterpret_cast<const float4*>(w + k * 32 + g * 4);
    float* dst = out + (size_t)out_idx[pair] * 32 + g * 4;
    red4(dst, v * wv.x, v * wv.y, v * wv.z, v * wv.w);
}

// ---------------- generic gather-GEMM-scatter ----------------
// C[out_idx[k,m], n0:n0+BN] += A_gathered[m, :] @ W[k][:, n0:n0+BN]
template<int CIN, int COUT, int BM, int BN, int BK, int TM, int TN>
__global__ __launch_bounds__(256)
void spconv_kernel(const float* __restrict__ feats,
                   const float* __restrict__ W,
                   const int* __restrict__ in_idx,
                   const int* __restrict__ out_idx,
                   float* __restrict__ out,
                   int M) {
    const int k  = blockIdx.z;
    const int m0 = blockIdx.x * BM;
    const int n0 = blockIdx.y * BN;
    const int tid = threadIdx.x;
    const int tx = tid & 15;      // 16 cols of threads
    const int ty = tid >> 4;      // 16 rows of threads

    __shared__ __align__(16) float As[BK][BM + 4];
    __shared__ __align__(16) float Bs[BK][BN];
    __shared__ int rows[BM];

    if (tid < BM) {
        int m = m0 + tid;
        rows[tid] = (m < M) ? in_idx[k * M + m] : -1;
    }

    float acc[TM][TN];
#pragma unroll
    for (int i = 0; i < TM; i++)
#pragma unroll
        for (int j = 0; j < TN; j++) acc[i][j] = 0.f;

    const float* Wk = W + (size_t)k * CIN * COUT;

    for (int k0 = 0; k0 < CIN; k0 += BK) {
        __syncthreads();
        // load A tile (gathered), BM*BK elems, coalesced along cin
#pragma unroll
        for (int t = 0; t < (BM * BK) / 256; t++) {
            int e = tid + t * 256;
            int r = e / BK, c = e % BK;
            int fr = rows[r];
            As[c][r] = (fr >= 0) ? feats[(size_t)fr * CIN + k0 + c] : 0.f;
        }
        // load W tile, BK*BN elems
#pragma unroll
        for (int t = 0; t < (BK * BN) / 256; t++) {
            int e = tid + t * 256;
            int c = e / BN, j = e % BN;
            Bs[c][j] = Wk[(size_t)(k0 + c) * COUT + n0 + j];
        }
        __syncthreads();
#pragma unroll
        for (int kk = 0; kk < BK; kk++) {
            float a[TM], b[TN];
            if (TM == 4) {
                float4 av = *reinterpret_cast<const float4*>(&As[kk][ty * 4]);
                a[0] = av.x; a[1] = av.y; a[2] = av.z; a[3] = av.w;
            } else {
#pragma unroll
                for (int i = 0; i < TM; i++) a[i] = As[kk][ty * TM + i];
            }
            if (TN == 4) {
                float4 bv = *reinterpret_cast<const float4*>(&Bs[kk][tx * 4]);
                b[0] = bv.x; b[1] = bv.y; b[2] = bv.z; b[3] = bv.w;
            } else {
                float2 bv = *reinterpret_cast<const float2*>(&Bs[kk][tx * 2]);
                b[0] = bv.x; b[1] = bv.y;
            }
#pragma unroll
            for (int i = 0; i < TM; i++)
#pragma unroll
                for (int j = 0; j < TN; j++) acc[i][j] += a[i] * b[j];
        }
    }

    // scatter with vector reductions
#pragma unroll
    for (int i = 0; i < TM; i++) {
        int m = m0 + ty * TM + i;
        if (m < M) {
            int orow = out_idx[k * M + m];
            float* dst = out + (size_t)orow * COUT + n0 + tx * TN;
            if (TN == 4) red4(dst, acc[i][0], acc[i][1], acc[i][2], acc[i][3]);
            else         red2(dst, acc[i][0], acc[i][1]);
        }
    }
}

// ---------------- elementwise / BN kernels ----------------
__global__ void relu_kernel(float* __restrict__ x, int n4) {
    int i = blockIdx.x * blockDim.x + threadIdx.x;
    if (i >= n4) return;
    float4 v = reinterpret_cast<float4*>(x)[i];
    v.x = fmaxf(v.x, 0.f); v.y = fmaxf(v.y, 0.f);
    v.z = fmaxf(v.z, 0.f); v.w = fmaxf(v.w, 0.f);
    reinterpret_cast<float4*>(x)[i] = v;
}

__global__ void zero_stats_kernel() {
    g_sum[threadIdx.x] = 0.f;
    g_sumsq[threadIdx.x] = 0.f;
}

__global__ void bn_stats_kernel(const float* __restrict__ x, int total, int cmask) {
    __shared__ float ssum[256], ssq[256];
    for (int c = threadIdx.x; c < 256; c += blockDim.x) { ssum[c] = 0.f; ssq[c] = 0.f; }
    __syncthreads();
    for (int e = blockIdx.x * blockDim.x + threadIdx.x; e < total; e += gridDim.x * blockDim.x) {
        float v = x[e];
        int c = e & cmask;
        atomicAdd(&ssum[c], v);
        atomicAdd(&ssq[c], v * v);
    }
    __syncthreads();
    for (int c = threadIdx.x; c <= cmask; c += blockDim.x) {
        atomicAdd(&g_sum[c], ssum[c]);
        atomicAdd(&g_sumsq[c], ssq[c]);
    }
}

__global__ void bn_relu_kernel(const float* __restrict__ x, float* __restrict__ y,
                               const float* __restrict__ gg, const float* __restrict__ bb,
                               float invN, int total, int cmask) {
    int e = blockIdx.x * blockDim.x + threadIdx.x;
    if (e >= total) return;
    int c = e & cmask;
    float mean = g_sum[c] * invN;
    float var  = g_sumsq[c] * invN - mean * mean;
    float s = rsqrtf(var + EPSv) * gg[c];
    float v = (x[e] - mean) * s + bb[c];
    y[e] = fmaxf(v, 0.f);
}

// ---------------- orchestration ----------------
extern "C" void kernel_launch(void* const* d_in, const int* in_sizes, int n_in,
                              void* d_out, int out_size) {
    const float* x_feats = (const float*)d_in[0];
    const float* w1a = (const float*)d_in[1];
    const float* w1b = (const float*)d_in[2];
    const float* w1c = (const float*)d_in[3];
    const float* w2  = (const float*)d_in[4];
    const float* w3a = (const float*)d_in[5];
    const float* w3b = (const float*)d_in[6];
    const float* bn1b_g = (const float*)d_in[7];
    const float* bn1b_b = (const float*)d_in[8];
    const float* bn1c_g = (const float*)d_in[9];
    const float* bn1c_b = (const float*)d_in[10];
    const float* bn3a_g = (const float*)d_in[11];
    const float* bn3a_b = (const float*)d_in[12];
    const float* bn3b_g = (const float*)d_in[13];
    const float* bn3b_b = (const float*)d_in[14];
    const int* km1a_in  = (const int*)d_in[15];
    const int* km1a_out = (const int*)d_in[16];
    const int* km1b_in  = (const int*)d_in[17];
    const int* km1b_out = (const int*)d_in[18];
    const int* km1c_in  = (const int*)d_in[19];
    const int* km1c_out = (const int*)d_in[20];
    const int* km2_in   = (const int*)d_in[21];
    const int* km2_out  = (const int*)d_in[22];
    const int* km3a_in  = (const int*)d_in[23];
    const int* km3a_out = (const int*)d_in[24];
    const int* km3b_in  = (const int*)d_in[25];
    const int* km3b_out = (const int*)d_in[26];

    float* out = (float*)d_out;
    float* x_e1 = out;                     // [N1, 32]
    float* x_e2 = out + (size_t)N1v * 32;  // [N2, 256]

    float *buf1, *buf2, *buf3, *buf4, *buf5;
    cudaGetSymbolAddress((void**)&buf1, g_buf1);
    cudaGetSymbolAddress((void**)&buf2, g_buf2);
    cudaGetSymbolAddress((void**)&buf3, g_buf3);
    cudaGetSymbolAddress((void**)&buf4, g_buf4);
    cudaGetSymbolAddress((void**)&buf5, g_buf5);

    const int STATS_GRID = 2048;

    // ---- enc1a: conv(1->32, k5) + relu ----
    cudaMemsetAsync(buf1, 0, (size_t)N1v * 32 * sizeof(float), 0);
    {
        int total = K5v * M1v;
        int threads = total * 8;
        conv1a_kernel<<<(threads + 255) / 256, 256>>>(x_feats, w1a, km1a_in, km1a_out, buf1, total, M1v);
        relu_kernel<<<(N1v * 32 / 4 + 255) / 256, 256>>>(buf1, N1v * 32 / 4);
    }

    // ---- enc1b: conv(32->32, k5) + BN + relu ----
    cudaMemsetAsync(buf2, 0, (size_t)N1v * 32 * sizeof(float), 0);
    spconv_kernel<32, 32, 64, 32, 32, 4, 2>
        <<<dim3((M2v + 63) / 64, 1, K5v), 256>>>(buf1, w1b, km1b_in, km1b_out, buf2, M2v);
    zero_stats_kernel<<<1, 256>>>();
    bn_stats_kernel<<<STATS_GRID, 256>>>(buf2, N1v * 32, 31);
    bn_relu_kernel<<<(N1v * 32 + 255) / 256, 256>>>(buf2, buf1, bn1b_g, bn1b_b, 1.0f / N1v, N1v * 32, 31);

    // ---- enc1c: conv(32->32, k5) + BN + relu -> x_e1 ----
    cudaMemsetAsync(buf2, 0, (size_t)N1v * 32 * sizeof(float), 0);
    spconv_kernel<32, 32, 64, 32, 32, 4, 2>
        <<<dim3((M2v + 63) / 64, 1, K5v), 256>>>(buf1, w1c, km1c_in, km1c_out, buf2, M2v);
    zero_stats_kernel<<<1, 256>>>();
    bn_stats_kernel<<<STATS_GRID, 256>>>(buf2, N1v * 32, 31);
    bn_relu_kernel<<<(N1v * 32 + 255) / 256, 256>>>(buf2, x_e1, bn1c_g, bn1c_b, 1.0f / N1v, N1v * 32, 31);

    // ---- conv2: conv(32->64, k3) (no activation) ----
    cudaMemsetAsync(buf3, 0, (size_t)N2v * 64 * sizeof(float), 0);
    spconv_kernel<32, 64, 64, 64, 32, 4, 4>
        <<<dim3((M3v + 63) / 64, 1, K3v), 256>>>(x_e1, w2, km2_in, km2_out, buf3, M3v);

    // ---- enc2a: conv(64->128, k3) + BN + relu ----
    cudaMemsetAsync(buf4, 0, (size_t)N2v * 128 * sizeof(float), 0);
    spconv_kernel<64, 128, 64, 64, 32, 4, 4>
        <<<dim3((M4v + 63) / 64, 2, K3v), 256>>>(buf3, w3a, km3a_in, km3a_out, buf4, M4v);
    zero_stats_kernel<<<1, 256>>>();
    bn_stats_kernel<<<STATS_GRID, 256>>>(buf4, N2v * 128, 127);
    bn_relu_kernel<<<(N2v * 128 + 255) / 256, 256>>>(buf4, buf4, bn3a_g, bn3a_b, 1.0f / N2v, N2v * 128, 127);

    // ---- enc2b: conv(128->256, k3) + BN + relu -> x_e2 ----
    cudaMemsetAsync(buf5, 0, (size_t)N2v * 256 * sizeof(float), 0);
    spconv_kernel<128, 256, 64, 64, 32, 4, 4>
        <<<dim3((M4v + 63) / 64, 4, K3v), 256>>>(buf4, w3b, km3b_in, km3b_out, buf5, M4v);
    zero_stats_kernel<<<1, 256>>>();
    bn_stats_kernel<<<STATS_GRID, 256>>>(buf5, N2v * 256, 255);
    bn_relu_kernel<<<(N2v * 256 + 255) / 256, 256>>>(buf5, x_e2, bn3b_g, bn3b_b, 1.0f / N2v, N2v * 256, 255);
}